// round 1
// baseline (speedup 1.0000x reference)
#include <cuda_runtime.h>
#include <cstdint>

// out = noise * gamma * sqrt(spread_bits(trunc(x * 2^14))) / 2^14
// spread_bits: bit k of w -> bit 2k (so value = sum over set bits of 4^k),
// which equals sum_k (2^k * bit_k)^2 from the reference's bit loop.

__device__ __forceinline__ unsigned spread16(unsigned v) {
    // v < 2^16; interleave with zeros
    v = (v | (v << 8)) & 0x00FF00FFu;
    v = (v | (v << 4)) & 0x0F0F0F0Fu;
    v = (v | (v << 2)) & 0x33333333u;
    v = (v | (v << 1)) & 0x55555555u;
    return v;
}

__device__ __forceinline__ float sigma_elem(float x) {
    // x in [0,1): trunc toward zero matches int cast
    int w = (int)(x * 16384.0f);
    unsigned acc = spread16((unsigned)w);
    // gamma / 2^14 = 0.05 / 16384
    return sqrtf((float)acc) * (0.05f / 16384.0f);
}

__global__ void weight_noise_kernel(const float4* __restrict__ x,
                                    const float4* __restrict__ noise,
                                    float4* __restrict__ out,
                                    int n4) {
    int idx = blockIdx.x * blockDim.x + threadIdx.x;
    int stride = gridDim.x * blockDim.x;
    for (int i = idx; i < n4; i += stride) {
        float4 xv = x[i];
        float4 nv = noise[i];
        float4 ov;
        ov.x = nv.x * sigma_elem(xv.x);
        ov.y = nv.y * sigma_elem(xv.y);
        ov.z = nv.z * sigma_elem(xv.z);
        ov.w = nv.w * sigma_elem(xv.w);
        out[i] = ov;
    }
}

extern "C" void kernel_launch(void* const* d_in, const int* in_sizes, int n_in,
                              void* d_out, int out_size) {
    const float4* x = (const float4*)d_in[0];
    const float4* noise = (const float4*)d_in[1];
    float4* out = (float4*)d_out;
    int n = in_sizes[0];
    int n4 = n / 4;  // 4096*8192 divisible by 4
    int threads = 256;
    int blocks = (n4 + threads - 1) / threads;
    if (blocks > 148 * 16) blocks = 148 * 16;  // cap; grid-stride covers rest
    weight_noise_kernel<<<blocks, threads>>>(x, noise, out, n4);
}

// round 2
// speedup vs baseline: 1.0335x; 1.0335x over previous
#include <cuda_runtime.h>
#include <cstdint>

// out = noise * gamma * sqrt(spread_bits(trunc(x * 2^14))) / 2^14
// spread_bits: bit k of w -> bit 2k, i.e. sum_k 4^k * bit_k = sum_k (2^k*bit_k)^2

__device__ __forceinline__ unsigned spread16(unsigned v) {
    v = (v | (v << 8)) & 0x00FF00FFu;
    v = (v | (v << 4)) & 0x0F0F0F0Fu;
    v = (v | (v << 2)) & 0x33333333u;
    v = (v | (v << 1)) & 0x55555555u;
    return v;
}

__device__ __forceinline__ float sigma_elem(float x) {
    int w = (int)(x * 16384.0f);
    unsigned acc = spread16((unsigned)w);
    return sqrtf((float)acc) * (0.05f / 16384.0f);
}

__device__ __forceinline__ float4 apply4(float4 xv, float4 nv) {
    float4 ov;
    ov.x = nv.x * sigma_elem(xv.x);
    ov.y = nv.y * sigma_elem(xv.y);
    ov.z = nv.z * sigma_elem(xv.z);
    ov.w = nv.w * sigma_elem(xv.w);
    return ov;
}

// Each thread handles 2 float4s spaced blockDim apart (coalesced). All 4 loads
// are issued up front (batched MLP) with streaming cache hint; stores stream too.
__global__ void __launch_bounds__(256) weight_noise_kernel(
        const float4* __restrict__ x,
        const float4* __restrict__ noise,
        float4* __restrict__ out,
        int n4) {
    int i0 = blockIdx.x * (blockDim.x * 2) + threadIdx.x;
    int i1 = i0 + blockDim.x;

    if (i1 < n4) {
        float4 x0 = __ldcs(x + i0);
        float4 x1 = __ldcs(x + i1);
        float4 n0 = __ldcs(noise + i0);
        float4 n1 = __ldcs(noise + i1);
        __stcs(out + i0, apply4(x0, n0));
        __stcs(out + i1, apply4(x1, n1));
    } else if (i0 < n4) {
        float4 x0 = __ldcs(x + i0);
        float4 n0 = __ldcs(noise + i0);
        __stcs(out + i0, apply4(x0, n0));
    }
}

extern "C" void kernel_launch(void* const* d_in, const int* in_sizes, int n_in,
                              void* d_out, int out_size) {
    const float4* x = (const float4*)d_in[0];
    const float4* noise = (const float4*)d_in[1];
    float4* out = (float4*)d_out;
    int n = in_sizes[0];
    int n4 = n / 4;                       // 4096*8192 divisible by 4
    int threads = 256;
    int per_block = threads * 2;          // 2 float4 per thread
    int blocks = (n4 + per_block - 1) / per_block;
    weight_noise_kernel<<<blocks, threads>>>(x, noise, out, n4);
}

// round 3
// speedup vs baseline: 1.0372x; 1.0036x over previous
#include <cuda_runtime.h>
#include <cstdint>

// out = noise * gamma * sqrt(spread_bits(trunc(x * 2^14))) / 2^14
// spread_bits: bit k of w -> bit 2k, i.e. sum_k 4^k * bit_k = sum_k (2^k*bit_k)^2

__device__ __forceinline__ unsigned spread16(unsigned v) {
    v = (v | (v << 8)) & 0x00FF00FFu;
    v = (v | (v << 4)) & 0x0F0F0F0Fu;
    v = (v | (v << 2)) & 0x33333333u;
    v = (v | (v << 1)) & 0x55555555u;
    return v;
}

__device__ __forceinline__ float sigma_elem(float x) {
    int w = (int)(x * 16384.0f);
    unsigned acc = spread16((unsigned)w);
    return sqrtf((float)acc) * (0.05f / 16384.0f);
}

__device__ __forceinline__ float4 apply4(float4 xv, float4 nv) {
    float4 ov;
    ov.x = nv.x * sigma_elem(xv.x);
    ov.y = nv.y * sigma_elem(xv.y);
    ov.z = nv.z * sigma_elem(xv.z);
    ov.w = nv.w * sigma_elem(xv.w);
    return ov;
}

// 4 float4s per thread, strided by blockDim within the block's tile so each
// load instruction is fully coalesced. All 8 LDG.128 issued before compute
// (deep MLP); streaming cache policy since every byte is touched once.
__global__ void __launch_bounds__(256) weight_noise_kernel(
        const float4* __restrict__ x,
        const float4* __restrict__ noise,
        float4* __restrict__ out,
        int n4) {
    const int bs = 256;
    int base = blockIdx.x * (bs * 4) + threadIdx.x;
    int i0 = base;
    int i1 = base + bs;
    int i2 = base + 2 * bs;
    int i3 = base + 3 * bs;

    if (i3 < n4) {
        float4 x0 = __ldcs(x + i0);
        float4 x1 = __ldcs(x + i1);
        float4 x2 = __ldcs(x + i2);
        float4 x3 = __ldcs(x + i3);
        float4 n0 = __ldcs(noise + i0);
        float4 n1 = __ldcs(noise + i1);
        float4 n2 = __ldcs(noise + i2);
        float4 n3 = __ldcs(noise + i3);
        __stcs(out + i0, apply4(x0, n0));
        __stcs(out + i1, apply4(x1, n1));
        __stcs(out + i2, apply4(x2, n2));
        __stcs(out + i3, apply4(x3, n3));
    } else {
        #pragma unroll
        for (int k = 0; k < 4; k++) {
            int i = base + k * bs;
            if (i < n4) {
                float4 xv = __ldcs(x + i);
                float4 nv = __ldcs(noise + i);
                __stcs(out + i, apply4(xv, nv));
            }
        }
    }
}

extern "C" void kernel_launch(void* const* d_in, const int* in_sizes, int n_in,
                              void* d_out, int out_size) {
    const float4* x = (const float4*)d_in[0];
    const float4* noise = (const float4*)d_in[1];
    float4* out = (float4*)d_out;
    int n = in_sizes[0];
    int n4 = n / 4;                    // 4096*8192/4 = 8388608
    int threads = 256;
    int per_block = threads * 4;       // 4 float4 per thread
    int blocks = (n4 + per_block - 1) / per_block;   // 8192 exact
    weight_noise_kernel<<<blocks, threads>>>(x, noise, out, n4);
}